// round 8
// baseline (speedup 1.0000x reference)
#include <cuda_runtime.h>
#include <cuda_bf16.h>
#include <cstdint>
#include <cstddef>

#define BB 4
#define SS 2048
#define DD 1024
#define HH 16
#define AA 64

#define NX (BB*SS*DD)
#define NW (HH*DD*AA)
#define NP (BB*HH*SS*AA)

#define LOG2E 1.4426950408889634f

__device__ __nv_bfloat16 g_xh[3][NX], g_xl[3][NX];
__device__ __nv_bfloat16 g_wh[3][NW], g_wl[3][NW];
__device__ __nv_bfloat16 g_ph[3][NP], g_pl[3][NP];
__device__ int g_ctr[2];

// ---------------------------------------------------------------------------
__device__ __forceinline__ uint32_t smem_u32(const void* p) {
    uint32_t a;
    asm("{ .reg .u64 t; cvta.to.shared.u64 t, %1; cvt.u32.u64 %0, t; }" : "=r"(a) : "l"(p));
    return a;
}
__device__ __forceinline__ float ex2f(float x) {
    float r; asm("ex2.approx.f32 %0, %1;" : "=f"(r) : "f"(x)); return r;
}
__device__ __forceinline__ void mma16816(float* d, const uint32_t* a,
                                         uint32_t b0, uint32_t b1) {
    asm volatile(
        "mma.sync.aligned.m16n8k16.row.col.f32.bf16.bf16.f32 "
        "{%0,%1,%2,%3}, {%4,%5,%6,%7}, {%8,%9}, {%0,%1,%2,%3};"
        : "+f"(d[0]), "+f"(d[1]), "+f"(d[2]), "+f"(d[3])
        : "r"(a[0]), "r"(a[1]), "r"(a[2]), "r"(a[3]), "r"(b0), "r"(b1));
}
__device__ __forceinline__ void ldsm4(uint32_t* r, uint32_t addr) {
    asm volatile("ldmatrix.sync.aligned.m8n8.x4.shared.b16 {%0,%1,%2,%3}, [%4];"
        : "=r"(r[0]), "=r"(r[1]), "=r"(r[2]), "=r"(r[3]) : "r"(addr));
}
__device__ __forceinline__ void ldsm4t(uint32_t* r, uint32_t addr) {
    asm volatile("ldmatrix.sync.aligned.m8n8.x4.trans.shared.b16 {%0,%1,%2,%3}, [%4];"
        : "=r"(r[0]), "=r"(r[1]), "=r"(r[2]), "=r"(r[3]) : "r"(addr));
}
__device__ __forceinline__ void split_pack(float x0, float x1, uint32_t& h, uint32_t& l) {
    uint32_t hh;
    asm("cvt.rn.bf16x2.f32 %0, %1, %2;" : "=r"(hh) : "f"(x1), "f"(x0));
    float f0 = __uint_as_float(hh << 16);
    float f1 = __uint_as_float(hh & 0xffff0000u);
    float r0 = x0 - f0, r1 = x1 - f1;
    asm("cvt.rn.bf16x2.f32 %0, %1, %2;" : "=r"(l) : "f"(r1), "f"(r0));
    h = hh;
}
__device__ __forceinline__ void cpa16(uint32_t dst, const void* src) {
    asm volatile("cp.async.cg.shared.global [%0], [%1], 16;" :: "r"(dst), "l"(src));
}
#define CP_COMMIT()  asm volatile("cp.async.commit_group;" ::: "memory")
#define CP_WAIT(N)   asm volatile("cp.async.wait_group %0;" :: "n"(N) : "memory")

// ---------------------------------------------------------------------------
// Stage 0: split fp32 -> bf16 hi/lo, 3 tensors per launch
// Wq (kind=1, which=0) pre-scaled by log2(e)
// ---------------------------------------------------------------------------
__global__ __launch_bounds__(256) void conv3(const float* __restrict__ a,
                                             const float* __restrict__ b,
                                             const float* __restrict__ c,
                                             int kind, int n4)
{
    int which = blockIdx.z;
    const float* in = (which == 0) ? a : (which == 1) ? b : c;
    __nv_bfloat16* hi = kind ? g_wh[which] : g_xh[which];
    __nv_bfloat16* lo = kind ? g_wl[which] : g_xl[which];
    float scale = (kind && which == 0) ? LOG2E : 1.0f;
    int i0 = blockIdx.x * 512 + threadIdx.x;
#pragma unroll
    for (int u = 0; u < 2; u++) {
        int idx = i0 + u * 256;
        if (idx < n4) {
            float4 v = ((const float4*)in)[idx];
            uint32_t h0, l0, h1, l1;
            split_pack(v.x * scale, v.y * scale, h0, l0);
            split_pack(v.z * scale, v.w * scale, h1, l1);
            ((uint2*)hi)[idx] = make_uint2(h0, h1);
            ((uint2*)lo)[idx] = make_uint2(l0, l1);
        }
    }
}

__global__ void zero_ctr() { g_ctr[0] = 0; g_ctr[1] = 0; }

// ---------------------------------------------------------------------------
// Stage 1: projection GEMM, persistent CTAs + cp.async double buffer
// tile: which = id/512, hp = (id%512)&7, m0 = ((id%512)>>3)*128
// ---------------------------------------------------------------------------
#define PX2 80
#define PW  272

static constexpr int PSXH = 0;
static constexpr int PSXL = PSXH + 128 * PX2;
static constexpr int PSWH = PSXL + 128 * PX2;
static constexpr int PSWL = PSWH + 32 * PW;
static constexpr int PSTG = PSWL + 32 * PW;     // 37888
static constexpr int PROJ_SMEM = 2 * PSTG;      // 75776
static constexpr int PROJ_TILES = 3 * 8 * 64;   // 1536

__device__ __forceinline__ void proj_issue(
    uint32_t sbase, const __nv_bfloat16* Xh, const __nv_bfloat16* Xl,
    const __nv_bfloat16* Wh_, const __nv_bfloat16* Wl_,
    int m0, int h0, int k0, int t)
{
#pragma unroll
    for (int j = 0; j < 2; j++) {
        int idx = t + 256 * j;
        int r = idx >> 2, c8 = (idx & 3) * 8;
        size_t go = (size_t)(m0 + r) * DD + k0 + c8;
        uint32_t so = sbase + r * PX2 + c8 * 2;
        cpa16(so + PSXH, Xh + go);
        cpa16(so + PSXL, Xl + go);
    }
#pragma unroll
    for (int j = 0; j < 2; j++) {
        int idx = t + 256 * j;
        int r = idx >> 4, c8 = (idx & 15) * 8;
        int hh_ = h0 + (c8 >> 6), a = c8 & 63;
        size_t go = ((size_t)hh_ * DD + (k0 + r)) * AA + a;
        uint32_t so = sbase + r * PW + c8 * 2;
        cpa16(so + PSWH, Wh_ + go);
        cpa16(so + PSWL, Wl_ + go);
    }
}

__global__ __launch_bounds__(256, 2) void proj_mma(
    const float* __restrict__ bq, const float* __restrict__ bk,
    const float* __restrict__ bv)
{
    extern __shared__ char smc[];
    __shared__ int s_tile;
    const uint32_t sb = smem_u32(smc);
    const int t = threadIdx.x, lane = t & 31, w = t >> 5;

    const int lr  = lane & 7;
    const int grp = lane >> 3;
    const uint32_t a_row = 16 * w + lr + (grp & 1) * 8;
    const uint32_t a_cb  = (grp >> 1) * 16;
    const uint32_t wb_row = lr + (grp & 1) * 8;
    const uint32_t wb_cb  = (grp >> 1) * 16;

    for (;;) {
        __syncthreads();
        if (t == 0) s_tile = atomicAdd(&g_ctr[0], 1);
        __syncthreads();
        const int tile = s_tile;
        if (tile >= PROJ_TILES) break;

        const int which = tile >> 9;
        const int rem = tile & 511;
        const int h0 = (rem & 7) * 2;
        const int m0 = (rem >> 3) * 128;
        const float* bias = (which == 0) ? bq : (which == 1) ? bk : bv;
        const float bscale = (which == 0) ? LOG2E : 1.0f;

        const __nv_bfloat16* Xh = g_xh[which];
        const __nv_bfloat16* Xl = g_xl[which];
        const __nv_bfloat16* Wh_ = g_wh[which];
        const __nv_bfloat16* Wl_ = g_wl[which];
        __nv_bfloat16* Oh = g_ph[which];
        __nv_bfloat16* Ol = g_pl[which];

        float acc[16][4];
#pragma unroll
        for (int i = 0; i < 16; i++)
#pragma unroll
            for (int j = 0; j < 4; j++) acc[i][j] = 0.f;

        proj_issue(sb, Xh, Xl, Wh_, Wl_, m0, h0, 0, t);
        CP_COMMIT();

        const int NIT = DD / 32;
        for (int it = 0; it < NIT; it++) {
            __syncthreads();
            if (it + 1 < NIT) {
                proj_issue(sb + ((it + 1) & 1) * PSTG, Xh, Xl, Wh_, Wl_, m0, h0, (it + 1) * 32, t);
                CP_COMMIT();
                CP_WAIT(1);
            } else {
                CP_WAIT(0);
            }
            __syncthreads();

            const uint32_t st = sb + (it & 1) * PSTG;
            const uint32_t axh = st + PSXH + a_row * PX2 + a_cb;
            const uint32_t axl = st + PSXL + a_row * PX2 + a_cb;
#pragma unroll
            for (int ks = 0; ks < 2; ks++) {
                uint32_t xh[4], xl[4];
                ldsm4(xh, axh + ks * 32);
                ldsm4(xl, axl + ks * 32);
#pragma unroll
                for (int npp = 0; npp < 4; npp++) {
                    uint32_t wh[2][4], wl[2][4];
#pragma unroll
                    for (int u = 0; u < 2; u++) {
                        int np = npp * 2 + u;
                        uint32_t waddr = st + (ks * 16 + wb_row) * PW + np * 32 + wb_cb;
                        ldsm4t(wh[u], PSWH + waddr);
                        ldsm4t(wl[u], PSWL + waddr);
                    }
                    float* a0 = acc[4*npp+0]; float* a1 = acc[4*npp+1];
                    float* a2 = acc[4*npp+2]; float* a3 = acc[4*npp+3];
                    mma16816(a0, xh, wh[0][0], wh[0][1]);
                    mma16816(a1, xh, wh[0][2], wh[0][3]);
                    mma16816(a2, xh, wh[1][0], wh[1][1]);
                    mma16816(a3, xh, wh[1][2], wh[1][3]);
                    mma16816(a0, xh, wl[0][0], wl[0][1]);
                    mma16816(a1, xh, wl[0][2], wl[0][3]);
                    mma16816(a2, xh, wl[1][0], wl[1][1]);
                    mma16816(a3, xh, wl[1][2], wl[1][3]);
                    mma16816(a0, xl, wh[0][0], wh[0][1]);
                    mma16816(a1, xl, wh[0][2], wh[0][3]);
                    mma16816(a2, xl, wh[1][0], wh[1][1]);
                    mma16816(a3, xl, wh[1][2], wh[1][3]);
                }
            }
        }

        const int bidx = m0 / SS;
        const int srow = m0 % SS;
        const int rlo = lane >> 2;
        const int cp  = 2 * (lane & 3);
#pragma unroll
        for (int j = 0; j < 16; j++) {
            int n = 8 * j + cp;
            int hh_ = h0 + (n >> 6);
            int a = n & 63;
            float b0 = bias[hh_ * AA + a] * bscale, b1 = bias[hh_ * AA + a + 1] * bscale;
            int s0 = srow + 16 * w + rlo;
            size_t o0 = ((size_t)(bidx * HH + hh_) * SS + s0) * AA + a;
            size_t o1 = o0 + (size_t)8 * AA;
            uint32_t hv, lv;
            split_pack(acc[j][0] + b0, acc[j][1] + b1, hv, lv);
            *(uint32_t*)(Oh + o0) = hv; *(uint32_t*)(Ol + o0) = lv;
            split_pack(acc[j][2] + b0, acc[j][3] + b1, hv, lv);
            *(uint32_t*)(Oh + o1) = hv; *(uint32_t*)(Ol + o1) = lv;
        }
    }
}

// ---------------------------------------------------------------------------
// Stage 2: flash attention, persistent CTAs, cp.async double buffer,
// distance-4 MMA interleave, ex2-based softmax (Q pre-scaled by log2e)
// ---------------------------------------------------------------------------
#define PITCH 144

static constexpr int AKH = 0;
static constexpr int AKL = AKH + 64 * PITCH;
static constexpr int AVH = AKL + 64 * PITCH;
static constexpr int AVL = AVH + 64 * PITCH;
static constexpr int ASTG = AVL + 64 * PITCH;   // 36864
static constexpr int ASQH = 2 * ASTG;
static constexpr int ASQL = ASQH + 128 * PITCH;
static constexpr int ATTN_SMEM = ASQL + 128 * PITCH; // 110592
static constexpr int ATTN_TILES = 16 * 16 * 4;       // 1024

__device__ __forceinline__ void attn_issue(
    uint32_t sbase, const __nv_bfloat16* kh, const __nv_bfloat16* kl,
    const __nv_bfloat16* vh, const __nv_bfloat16* vl, int t)
{
#pragma unroll
    for (int j = 0; j < 2; j++) {
        int idx = t + 256 * j;
        int r = idx >> 3, c8 = (idx & 7) * 8;
        size_t go = (size_t)r * AA + c8;
        uint32_t so = sbase + r * PITCH + c8 * 2;
        cpa16(so + AKH, kh + go);
        cpa16(so + AKL, kl + go);
        cpa16(so + AVH, vh + go);
        cpa16(so + AVL, vl + go);
    }
}

__global__ __launch_bounds__(256, 2) void attn_mma(float* __restrict__ out)
{
    extern __shared__ char smc[];
    __shared__ int s_tile;
    const uint32_t sb = smem_u32(smc);
    const int t = threadIdx.x, lane = t & 31, w = t >> 5;

    const int lr  = lane & 7;
    const int grp = lane >> 3;
    const uint32_t a_row = 16 * w + lr + (grp & 1) * 8;
    const uint32_t a_cb  = (grp >> 1) * 16;
    const uint32_t kb_row = lr + (grp >> 1) * 8;
    const uint32_t kb_cb  = (grp & 1) * 16;
    const uint32_t vb_row = lr + (grp & 1) * 8;
    const uint32_t vb_cb  = (grp >> 1) * 16;
    const uint32_t aqh = sb + ASQH + a_row * PITCH + a_cb;
    const uint32_t aql = sb + ASQL + a_row * PITCH + a_cb;

    for (;;) {
        __syncthreads();
        if (t == 0) s_tile = atomicAdd(&g_ctr[1], 1);
        __syncthreads();
        const int tile = s_tile;
        if (tile >= ATTN_TILES) break;

        const int qt = tile & 15, h = (tile >> 4) & 15, b = tile >> 8;
        const size_t bh = (size_t)(b * HH + h) * SS;

        const __nv_bfloat16* kh0 = g_ph[1] + bh * AA;
        const __nv_bfloat16* kl0 = g_pl[1] + bh * AA;
        const __nv_bfloat16* vh0 = g_ph[2] + bh * AA;
        const __nv_bfloat16* vl0 = g_pl[2] + bh * AA;

        attn_issue(sb, kh0, kl0, vh0, vl0, t);
        CP_COMMIT();

        {
            const __nv_bfloat16* qh = g_ph[0] + (bh + qt * 128) * AA;
            const __nv_bfloat16* ql = g_pl[0] + (bh + qt * 128) * AA;
#pragma unroll
            for (int j = 0; j < 4; j++) {
                int idx = t + 256 * j;
                int r = idx >> 3, c = (idx & 7) * 8;
                *(uint4*)(smc + ASQH + r * PITCH + c * 2) = *(const uint4*)(qh + (size_t)r * AA + c);
                *(uint4*)(smc + ASQL + r * PITCH + c * 2) = *(const uint4*)(ql + (size_t)r * AA + c);
            }
        }

        float oacc[8][4];
#pragma unroll
        for (int i = 0; i < 8; i++)
#pragma unroll
            for (int j = 0; j < 4; j++) oacc[i][j] = 0.f;
        float lA = 0.f, lB = 0.f, CA = 0.f, CB = 0.f;

        const int NIT = SS / 64;
        for (int kt = 0; kt < NIT; kt++) {
            __syncthreads();
            if (kt + 1 < NIT) {
                size_t ko = (size_t)(kt + 1) * 64 * AA;
                attn_issue(sb + ((kt + 1) & 1) * ASTG, kh0 + ko, kl0 + ko, vh0 + ko, vl0 + ko, t);
                CP_COMMIT();
                CP_WAIT(1);
            } else {
                CP_WAIT(0);
            }
            __syncthreads();

            const uint32_t st = sb + (kt & 1) * ASTG;

            float sacc[8][4];
#pragma unroll
            for (int i = 0; i < 8; i++)
#pragma unroll
                for (int j = 0; j < 4; j++) sacc[i][j] = 0.f;

            // ---- S = Q K^T, distance-4 interleave ----
#pragma unroll
            for (int ks = 0; ks < 4; ks++) {
                uint32_t qh[4], ql[4];
                ldsm4(qh, aqh + ks * 32);
                ldsm4(ql, aql + ks * 32);
#pragma unroll
                for (int npp = 0; npp < 2; npp++) {
                    uint32_t kh[2][4], kl[2][4];
#pragma unroll
                    for (int u = 0; u < 2; u++) {
                        int np = npp * 2 + u;
                        uint32_t kaddr = st + (np * 16 + kb_row) * PITCH + ks * 32 + kb_cb;
                        ldsm4(kh[u], AKH + kaddr);
                        ldsm4(kl[u], AKL + kaddr);
                    }
                    float* a0 = sacc[4*npp+0]; float* a1 = sacc[4*npp+1];
                    float* a2 = sacc[4*npp+2]; float* a3 = sacc[4*npp+3];
                    mma16816(a0, qh, kh[0][0], kh[0][1]);
                    mma16816(a1, qh, kh[0][2], kh[0][3]);
                    mma16816(a2, qh, kh[1][0], kh[1][1]);
                    mma16816(a3, qh, kh[1][2], kh[1][3]);
                    mma16816(a0, qh, kl[0][0], kl[0][1]);
                    mma16816(a1, qh, kl[0][2], kl[0][3]);
                    mma16816(a2, qh, kl[1][0], kl[1][1]);
                    mma16816(a3, qh, kl[1][2], kl[1][3]);
                    mma16816(a0, ql, kh[0][0], kh[0][1]);
                    mma16816(a1, ql, kh[0][2], kh[0][3]);
                    mma16816(a2, ql, kh[1][0], kh[1][1]);
                    mma16816(a3, ql, kh[1][2], kh[1][3]);
                }
            }

            // ---- softmax in log2 units (scores pre-scaled by log2e) ----
            if (kt == 0) {
                float mA = -1e30f, mB = -1e30f;
#pragma unroll
                for (int i = 0; i < 8; i++) {
                    mA = fmaxf(mA, fmaxf(sacc[i][0], sacc[i][1]));
                    mB = fmaxf(mB, fmaxf(sacc[i][2], sacc[i][3]));
                }
                mA = fmaxf(mA, __shfl_xor_sync(0xffffffffu, mA, 1));
                mA = fmaxf(mA, __shfl_xor_sync(0xffffffffu, mA, 2));
                mB = fmaxf(mB, __shfl_xor_sync(0xffffffffu, mB, 1));
                mB = fmaxf(mB, __shfl_xor_sync(0xffffffffu, mB, 2));
                CA = mA; CB = mB;
            }
#pragma unroll
            for (int i = 0; i < 8; i++) {
                sacc[i][0] = ex2f(sacc[i][0] - CA);
                sacc[i][1] = ex2f(sacc[i][1] - CA);
                sacc[i][2] = ex2f(sacc[i][2] - CB);
                sacc[i][3] = ex2f(sacc[i][3] - CB);
                lA += sacc[i][0] + sacc[i][1];
                lB += sacc[i][2] + sacc[i][3];
            }

            // ---- O += P V, distance-4 interleave ----
#pragma unroll
            for (int ks = 0; ks < 4; ks++) {
                uint32_t ph[4], pl[4];
                split_pack(sacc[2*ks][0],   sacc[2*ks][1],   ph[0], pl[0]);
                split_pack(sacc[2*ks][2],   sacc[2*ks][3],   ph[1], pl[1]);
                split_pack(sacc[2*ks+1][0], sacc[2*ks+1][1], ph[2], pl[2]);
                split_pack(sacc[2*ks+1][2], sacc[2*ks+1][3], ph[3], pl[3]);
#pragma unroll
                for (int npp = 0; npp < 2; npp++) {
                    uint32_t vh[2][4], vl[2][4];
#pragma unroll
                    for (int u = 0; u < 2; u++) {
                        int np = npp * 2 + u;
                        uint32_t vaddr = st + (ks * 16 + vb_row) * PITCH + np * 32 + vb_cb;
                        ldsm4t(vh[u], AVH + vaddr);
                        ldsm4t(vl[u], AVL + vaddr);
                    }
                    float* a0 = oacc[4*npp+0]; float* a1 = oacc[4*npp+1];
                    float* a2 = oacc[4*npp+2]; float* a3 = oacc[4*npp+3];
                    mma16816(a0, ph, vh[0][0], vh[0][1]);
                    mma16816(a1, ph, vh[0][2], vh[0][3]);
                    mma16816(a2, ph, vh[1][0], vh[1][1]);
                    mma16816(a3, ph, vh[1][2], vh[1][3]);
                    mma16816(a0, ph, vl[0][0], vl[0][1]);
                    mma16816(a1, ph, vl[0][2], vl[0][3]);
                    mma16816(a2, ph, vl[1][0], vl[1][1]);
                    mma16816(a3, ph, vl[1][2], vl[1][3]);
                    mma16816(a0, pl, vh[0][0], vh[0][1]);
                    mma16816(a1, pl, vh[0][2], vh[0][3]);
                    mma16816(a2, pl, vh[1][0], vh[1][1]);
                    mma16816(a3, pl, vh[1][2], vh[1][3]);
                }
            }
        }

        // ---- epilogue ----
        float lAs = lA + __shfl_xor_sync(0xffffffffu, lA, 1);
        lAs += __shfl_xor_sync(0xffffffffu, lAs, 2);
        float lBs = lB + __shfl_xor_sync(0xffffffffu, lB, 1);
        lBs += __shfl_xor_sync(0xffffffffu, lBs, 2);
        float invA = 1.f / lAs, invB = 1.f / lBs;

        int rA = qt * 128 + 16 * w + (lane >> 2);
        int col = 2 * (lane & 3);
        float* oA = out + ((size_t)(b * SS + rA)) * (HH * AA) + h * AA + col;
        float* oB = oA + 8 * (HH * AA);
#pragma unroll
        for (int j = 0; j < 8; j++) {
            float2 vA = make_float2(oacc[j][0] * invA, oacc[j][1] * invA);
            float2 vB = make_float2(oacc[j][2] * invB, oacc[j][3] * invB);
            *(float2*)(oA + j * 8) = vA;
            *(float2*)(oB + j * 8) = vB;
        }
    }
}

// ---------------------------------------------------------------------------

extern "C" void kernel_launch(void* const* d_in, const int* in_sizes, int n_in,
                              void* d_out, int out_size)
{
    const float* q  = (const float*)d_in[0];
    const float* k  = (const float*)d_in[1];
    const float* v  = (const float*)d_in[2];
    const float* Wq = (const float*)d_in[3];
    const float* bq = (const float*)d_in[4];
    const float* Wk = (const float*)d_in[5];
    const float* bk = (const float*)d_in[6];
    const float* Wv = (const float*)d_in[7];
    const float* bv = (const float*)d_in[8];
    float* out = (float*)d_out;

    cudaFuncSetAttribute(proj_mma, cudaFuncAttributeMaxDynamicSharedMemorySize, PROJ_SMEM);
    cudaFuncSetAttribute(attn_mma, cudaFuncAttributeMaxDynamicSharedMemorySize, ATTN_SMEM);

    dim3 cgx(NX / 4 / 512, 1, 3);
    conv3<<<cgx, 256>>>(q, k, v, 0, NX / 4);
    dim3 cgw(NW / 4 / 512, 1, 3);
    conv3<<<cgw, 256>>>(Wq, Wk, Wv, 1, NW / 4);
    zero_ctr<<<1, 1>>>();

    proj_mma<<<296, 256, PROJ_SMEM>>>(bq, bk, bv);
    attn_mma<<<296, 256, ATTN_SMEM>>>(out);
}